// round 17
// baseline (speedup 1.0000x reference)
#include <cuda_runtime.h>
#include <cuda_bf16.h>
#include <math.h>

#define B   64
#define NT  20000
#define NT1 20001
#define H4  1024
#define HD  256
#define Y_SZ    (B*NT1)
#define ENC_OFF Y_SZ
#define DEC_OFF (Y_SZ + B*HD)

// ---------------- scratch (device globals; no allocations) -----------------
__device__ float g_counts[NT*B];                 // [tag][batch]
__device__ int   g_istat[128];                   // [0:64) sum, [64:128) sumsq
__device__ float g_accum[B*H4];                  // GEMM1 split-K accumulator
__device__ float g_h2[B*H4], g_h3[B*H4], g_encb[B*HD];
__device__ __align__(16) __nv_bfloat16 g_ddh[B*H4], g_ddl[B*H4];
__device__ float g_pbuf[32*B*H4];                // small-GEMM split-K partials

__device__ __forceinline__ float gelu_exact(float x){
    return 0.5f * x * (1.0f + erff(x * 0.70710678118654752f));
}

// ---------------- mma.sync helpers (m16n8k16 bf16, row.col) ------------------
__device__ __forceinline__ void ldm_x4(unsigned r[4], unsigned addr){
    asm volatile("ldmatrix.sync.aligned.m8n8.x4.shared.b16 {%0,%1,%2,%3}, [%4];"
        : "=r"(r[0]),"=r"(r[1]),"=r"(r[2]),"=r"(r[3]) : "r"(addr));
}
__device__ __forceinline__ void ldm_x2t(unsigned r[2], unsigned addr){
    asm volatile("ldmatrix.sync.aligned.m8n8.x2.trans.shared.b16 {%0,%1}, [%2];"
        : "=r"(r[0]),"=r"(r[1]) : "r"(addr));
}
__device__ __forceinline__ void mma_bf(float c[4], const unsigned a[4], const unsigned b[2]){
    asm volatile("mma.sync.aligned.m16n8k16.row.col.f32.bf16.bf16.f32 "
        "{%0,%1,%2,%3},{%4,%5,%6,%7},{%8,%9},{%0,%1,%2,%3};"
        : "+f"(c[0]),"+f"(c[1]),"+f"(c[2]),"+f"(c[3])
        : "r"(a[0]),"r"(a[1]),"r"(a[2]),"r"(a[3]),"r"(b[0]),"r"(b[1]));
}
__device__ __forceinline__ unsigned cat2(__nv_bfloat16 a, __nv_bfloat16 b){
    unsigned short ua = *reinterpret_cast<unsigned short*>(&a);
    unsigned short ub = *reinterpret_cast<unsigned short*>(&b);
    return ((unsigned)ub << 16) | ua;
}
__device__ __forceinline__ void split_bf(float v, __nv_bfloat16& h, __nv_bfloat16& l){
    h = __float2bfloat16(v);
    l = __float2bfloat16(v - __bfloat162float(h));
}

// R12 SMEM tile layout for k4 (per buffer): A 64x32 bf16 (stride 80B), B 32x128 (stride 272B)
#define OFF_AH 0
#define OFF_AL 5120
#define OFF_BH 10240
#define OFF_BL 18944
#define BUFB   28672

// shared mma core: 8 warps, warp owns M64 x N16 (4 m-tiles x 2 n-tiles), 2 k-steps
__device__ __forceinline__ void mma_block(float (&c)[4][2][4], unsigned base, int aoff, int boff){
    #pragma unroll
    for (int ks = 0; ks < 2; ks++){
        unsigned ah[4][4], al[4][4], bh[2][2], bl2[2][2];
        #pragma unroll
        for (int mt = 0; mt < 4; mt++){
            ldm_x4(ah[mt], base + OFF_AH + mt*1280 + aoff + ks*32);
            ldm_x4(al[mt], base + OFF_AL + mt*1280 + aoff + ks*32);
        }
        #pragma unroll
        for (int nt = 0; nt < 2; nt++){
            ldm_x2t(bh[nt],  base + OFF_BH + ks*4352 + boff + nt*16);
            ldm_x2t(bl2[nt], base + OFF_BL + ks*4352 + boff + nt*16);
        }
        #pragma unroll
        for (int mt = 0; mt < 4; mt++)
            #pragma unroll
            for (int nt = 0; nt < 2; nt++){
                mma_bf(c[mt][nt], ah[mt], bh[nt]);
                mma_bf(c[mt][nt], al[mt], bh[nt]);
                mma_bf(c[mt][nt], ah[mt], bl2[nt]);
            }
    }
}

// ---------------- K1: scatter counts + stats (fused) + zero accum -----------
// atomicAdd returns the OLD count; sum of (2*old+1) over all increments of an
// address equals final c^2 exactly, order-independent -> deterministic stats.
__global__ void k1_scatter(const int* __restrict__ tags){
    int p = blockIdx.x*256 + threadIdx.x;       // 8192 threads = B*128 exactly
    for (int z = p; z < B*H4; z += 8192) g_accum[z] = 0.0f;
    int b = p >> 7;
    const int* t = tags + p*16;
    int v[16];
    #pragma unroll
    for (int i = 0; i < 16; i++) v[i] = t[i];
    int isum_l = 0, isq_l = 0;
    #pragma unroll
    for (int i = 0; i < 16; i++){
        bool dup = false;
        #pragma unroll
        for (int s = 0; s < 16; s++) if (s < i) dup = dup || (v[s] == v[i]);
        if (!dup){
            float old = atomicAdd(&g_counts[v[i]*B + b], 1.0f);
            int co = __float2int_rn(old);
            isum_l += 1;
            isq_l  += 2*co + 1;
        }
    }
    atomicAdd(&g_istat[b], isum_l);
    atomicAdd(&g_istat[64 + b], isq_l);
}

// ---------------- K3: write y (output #1); computes mu/rstd inline ----------
__global__ void __launch_bounds__(256) k3_y(const float* __restrict__ fc,
                                            const float* __restrict__ lng,
                                            const float* __restrict__ lnb,
                                            float* __restrict__ y){
    __shared__ float t[64*65];
    __shared__ float mu_s[64], rs_s[64];
    int tid = threadIdx.x;
    int j0 = blockIdx.x * 64;
    if (tid < 64){
        float mu  = (float)g_istat[tid] / (float)NT;
        float var = (float)g_istat[64 + tid] / (float)NT - mu*mu;
        mu_s[tid] = mu; rs_s[tid] = rsqrtf(var + 1e-5f);
    }
    #pragma unroll
    for (int i = 0; i < 16; i++){
        int idx = i*256 + tid; int r = idx >> 6, b = idx & 63; int j = j0 + r;
        t[r*65 + b] = (j < NT) ? g_counts[j*B + b] : 0.0f;
    }
    __syncthreads();
    #pragma unroll
    for (int i = 0; i < 16; i++){
        int idx = i*256 + tid; int b = idx >> 6, r = idx & 63; int j = j0 + r;
        if (j < NT)
            y[(size_t)b*NT1 + 1 + j] = (t[r*65 + b] - mu_s[b]) * rs_s[b] * lng[j] + lnb[j];
    }
    if (blockIdx.x == 0 && tid < B) y[(size_t)tid*NT1] = fc[tid] * 0.01f;
}

// ---------------- K4: GEMM1 (R12 proven version, verbatim) ------------------
#define KB4  37
#define KP4  544
#define NCH4 17
__global__ void __launch_bounds__(256) k4_mma(const float* __restrict__ y,
                                              const float* __restrict__ w1){
    extern __shared__ __align__(16) char sm4[];
    int tid = threadIdx.x, lane = tid & 31, wid = tid >> 5;
    int cbase = blockIdx.x * 128;
    int k00 = blockIdx.y * KP4;
    unsigned smb = (unsigned)__cvta_generic_to_shared(sm4);

    float c[4][2][4];
    #pragma unroll
    for (int mt = 0; mt < 4; mt++)
        #pragma unroll
        for (int nt = 0; nt < 2; nt++)
            #pragma unroll
            for (int q = 0; q < 4; q++) c[mt][nt][q] = 0.0f;

    const int aoff = (lane & 15)*80 + (lane >> 4)*16;
    const int boff = (lane & 15)*272 + wid*32;

    float4 wreg[4]; float areg[8];

    auto LOADS = [&](int k0){
        #pragma unroll
        for (int i = 0; i < 4; i++){
            int idx = i*256 + tid; int r = idx >> 5, c4 = idx & 31;
            int k = k0 + r;
            wreg[i] = (k < NT1)
                ? *reinterpret_cast<const float4*>(w1 + (size_t)k*1024 + cbase + c4*4)
                : make_float4(0.f,0.f,0.f,0.f);
        }
        #pragma unroll
        for (int i = 0; i < 8; i++){
            int idx = i*256 + tid; int b = idx >> 5, cc = idx & 31;
            int k = k0 + cc;
            areg[i] = (k < NT1) ? y[(size_t)b*NT1 + k] : 0.f;
        }
    };
    auto STORES = [&](char* buf){
        #pragma unroll
        for (int i = 0; i < 4; i++){
            int idx = i*256 + tid; int r = idx >> 5, c4 = idx & 31;
            float4 v = wreg[i];
            __nv_bfloat16 h0,h1,h2,h3,l0,l1,l2,l3;
            split_bf(v.x,h0,l0); split_bf(v.y,h1,l1);
            split_bf(v.z,h2,l2); split_bf(v.w,h3,l3);
            *reinterpret_cast<uint2*>(buf + OFF_BH + r*272 + c4*8) = make_uint2(cat2(h0,h1), cat2(h2,h3));
            *reinterpret_cast<uint2*>(buf + OFF_BL + r*272 + c4*8) = make_uint2(cat2(l0,l1), cat2(l2,l3));
        }
        #pragma unroll
        for (int i = 0; i < 8; i++){
            int idx = i*256 + tid; int b = idx >> 5, cc = idx & 31;
            __nv_bfloat16 h, l; split_bf(areg[i], h, l);
            *reinterpret_cast<__nv_bfloat16*>(buf + OFF_AH + b*80 + cc*2) = h;
            *reinterpret_cast<__nv_bfloat16*>(buf + OFF_AL + b*80 + cc*2) = l;
        }
    };

    LOADS(k00); STORES(sm4); __syncthreads();
    for (int ch = 0; ch < NCH4; ch++){
        unsigned curoff = (unsigned)(ch & 1) * BUFB;
        if (ch + 1 < NCH4) LOADS(k00 + (ch + 1)*32);
        mma_block(c, smb + curoff, aoff, boff);
        if (ch + 1 < NCH4) STORES(sm4 + (BUFB - curoff));
        __syncthreads();
    }

    #pragma unroll
    for (int mt = 0; mt < 4; mt++)
        #pragma unroll
        for (int nt = 0; nt < 2; nt++){
            int r0 = mt*16 + (lane >> 2);
            int col = cbase + wid*16 + nt*8 + (lane & 3)*2;
            atomicAdd(&g_accum[r0*1024 + col],       c[mt][nt][0]);
            atomicAdd(&g_accum[r0*1024 + col + 1],   c[mt][nt][1]);
            atomicAdd(&g_accum[(r0+8)*1024 + col],     c[mt][nt][2]);
            atomicAdd(&g_accum[(r0+8)*1024 + col + 1], c[mt][nt][3]);
        }
}

// ---------------- K5 fused: finalize + gelu + LayerNorm -> h2 ---------------
__global__ void __launch_bounds__(256) k5_fused(const float* __restrict__ b1,
                                                const float* __restrict__ g2,
                                                const float* __restrict__ b2){
    __shared__ float r1[256], r2[256];
    int b = blockIdx.x, tid = threadIdx.x;
    float h[4]; float s_sum = 0.0f, s_sq = 0.0f;
    #pragma unroll
    for (int i = 0; i < 4; i++){
        int k = i*256 + tid;
        h[i] = gelu_exact(g_accum[b*1024 + k] + b1[k]);
        s_sum += h[i]; s_sq += h[i]*h[i];
    }
    r1[tid] = s_sum; r2[tid] = s_sq; __syncthreads();
    for (int o = 128; o > 0; o >>= 1){
        if (tid < o){ r1[tid] += r1[tid+o]; r2[tid] += r2[tid+o]; }
        __syncthreads();
    }
    float mu = r1[0] * (1.0f/1024.0f);
    float var = r2[0] * (1.0f/1024.0f) - mu*mu;
    float rs = rsqrtf(var + 1e-5f);
    #pragma unroll
    for (int i = 0; i < 4; i++){
        int k = i*256 + tid;
        g_h2[b*1024 + k] = (h[i] - mu)*rs*g2[k] + b2[k];
    }
}

// ---------------- small GEMM: split-K partial + reduce ----------------------
template<int K, int N, int KPER>
__global__ void __launch_bounds__(256) sg_part(const float* __restrict__ A,
                                               const float* __restrict__ W,
                                               float* __restrict__ P){
    __shared__ float a_s[64*32];
    __shared__ float w_s[32*64];
    int tid = threadIdx.x, lane = tid & 31, wid = tid >> 5;
    int cbase = blockIdx.x*64, kbase = blockIdx.y*KPER;
    float acc[8][2] = {};
    for (int kc = kbase; kc < kbase + KPER; kc += 32){
        #pragma unroll
        for (int i = 0; i < 8; i++){
            int idx = i*256 + tid; int b = idx >> 5, kk = idx & 31;
            a_s[b*32 + kk] = A[b*K + kc + kk];
        }
        #pragma unroll
        for (int i = 0; i < 8; i++){
            int idx = i*256 + tid; int kk = idx >> 6, c = idx & 63;
            w_s[kk*64 + c] = W[(size_t)(kc + kk)*N + cbase + c];
        }
        __syncthreads();
        #pragma unroll
        for (int kk = 0; kk < 32; kk++){
            float av[8], wv0, wv1;
            #pragma unroll
            for (int i = 0; i < 8; i++) av[i] = a_s[(wid*8 + i)*32 + kk];
            wv0 = w_s[kk*64 + lane]; wv1 = w_s[kk*64 + lane + 32];
            #pragma unroll
            for (int i = 0; i < 8; i++){
                acc[i][0] += av[i]*wv0;
                acc[i][1] += av[i]*wv1;
            }
        }
        __syncthreads();
    }
    #pragma unroll
    for (int i = 0; i < 8; i++){
        P[blockIdx.y*(64*N) + (wid*8 + i)*N + cbase + lane]      = acc[i][0];
        P[blockIdx.y*(64*N) + (wid*8 + i)*N + cbase + lane + 32] = acc[i][1];
    }
}

template<int S, int N, bool ACT>
__global__ void sg_reduce(const float* __restrict__ P, const float* __restrict__ bias,
                          float* __restrict__ out, float* __restrict__ out2){
    int i = blockIdx.x*256 + threadIdx.x;
    if (i >= 64*N) return;
    float s = bias[i % N];
    #pragma unroll
    for (int p = 0; p < S; p++) s += P[p*64*N + i];
    if (ACT) s = gelu_exact(s);
    out[i] = s;
    if (out2) out2[i] = s;
}

// reduce + gelu + bf16-split for the decoder input dd
__global__ void sg_reduce_dd(const float* __restrict__ P, const float* __restrict__ bias){
    int i = blockIdx.x*256 + threadIdx.x;
    if (i >= 64*1024) return;
    float s = bias[i & 1023];
    #pragma unroll
    for (int p = 0; p < 8; p++) s += P[p*64*1024 + i];
    s = gelu_exact(s);
    __nv_bfloat16 h, l; split_bf(s, h, l);
    g_ddh[i] = h;
    g_ddl[i] = l;
}

// ---------------- K10: decoder GEMM dd[64,1024] @ wd2[1024,20001] -----------
// NB=64 cols/CTA, full K=1024 (32 chunks), direct store + bias. Grid 313.
// B tile stride 144 bytes (16*9 -> every ldmatrix address 16B-aligned).
#define K10_A(i)  ((unsigned)(i)*10240u)
#define K10_B(i)  (20480u + (unsigned)(i)*9216u)
#define K10_SMEM  38912
__global__ void __launch_bounds__(256) k10_mma(const float* __restrict__ wd2,
                                               const float* __restrict__ bd2,
                                               float* __restrict__ dec){
    extern __shared__ __align__(16) char sm4[];
    int tid = threadIdx.x, lane = tid & 31, wid = tid >> 5;
    int cbase = blockIdx.x * 64;
    unsigned smb = (unsigned)__cvta_generic_to_shared(sm4);

    float c[4][4];
    #pragma unroll
    for (int mt = 0; mt < 4; mt++)
        #pragma unroll
        for (int q = 0; q < 4; q++) c[mt][q] = 0.0f;

    const int aoff = (lane & 15)*80 + (lane >> 4)*16;
    const int boff = (lane & 15)*144 + wid*16;    // 144 = 16*9, aligned
    const int ab = tid >> 2, ac8 = (tid & 3)*8;

    uint4 ahreg, alreg; float wr[8];

    auto LOADS = [&](int k0){
        ahreg = *reinterpret_cast<const uint4*>(g_ddh + ab*1024 + k0 + ac8);
        alreg = *reinterpret_cast<const uint4*>(g_ddl + ab*1024 + k0 + ac8);
        #pragma unroll
        for (int i = 0; i < 4; i++){
            int idx = i*256 + tid; int r = idx >> 5, cp = idx & 31;
            int n0 = cbase + cp*2;
            const float* src = wd2 + (size_t)(k0 + r)*NT1 + n0;
            wr[2*i]   = (n0     < NT1) ? src[0] : 0.f;
            wr[2*i+1] = (n0 + 1 < NT1) ? src[1] : 0.f;
        }
    };
    auto STORES = [&](int bufi){
        char* abuf = sm4 + K10_A(bufi);
        *reinterpret_cast<uint4*>(abuf + ab*80 + ac8*2) = ahreg;
        *reinterpret_cast<uint4*>(abuf + 5120 + ab*80 + ac8*2) = alreg;
        char* bbuf = sm4 + K10_B(bufi);
        #pragma unroll
        for (int i = 0; i < 4; i++){
            int idx = i*256 + tid; int r = idx >> 5, cp = idx & 31;
            __nv_bfloat16 h0,h1,l0,l1;
            split_bf(wr[2*i], h0, l0); split_bf(wr[2*i+1], h1, l1);
            *reinterpret_cast<unsigned*>(bbuf + r*144 + cp*4)        = cat2(h0, h1);
            *reinterpret_cast<unsigned*>(bbuf + 4608 + r*144 + cp*4) = cat2(l0, l1);
        }
    };

    LOADS(0); STORES(0); __syncthreads();
    for (int ch = 0; ch < 32; ch++){
        int cur = ch & 1;
        if (ch + 1 < 32) LOADS((ch + 1)*32);
        unsigned aB = smb + K10_A(cur);
        unsigned bB = smb + K10_B(cur);
        #pragma unroll
        for (int ks = 0; ks < 2; ks++){
            unsigned ah[4][4], al[4][4], bh[2], bl2[2];
            #pragma unroll
            for (int mt = 0; mt < 4; mt++){
                ldm_x4(ah[mt], aB + mt*1280 + aoff + ks*32);
                ldm_x4(al[mt], aB + 5120 + mt*1280 + aoff + ks*32);
            }
            ldm_x2t(bh,  bB + ks*2304 + boff);
            ldm_x2t(bl2, bB + 4608 + ks*2304 + boff);
            #pragma unroll
            for (int mt = 0; mt < 4; mt++){
                mma_bf(c[mt], ah[mt], bh);
                mma_bf(c[mt], al[mt], bh);
                mma_bf(c[mt], ah[mt], bl2);
            }
        }
        __syncthreads();
        if (ch + 1 < 32){ STORES(cur ^ 1); __syncthreads(); }
    }

    // epilogue: SCALAR stores only (NT1 odd -> rows not 8B-aligned)
    #pragma unroll
    for (int mt = 0; mt < 4; mt++){
        int r0 = mt*16 + (lane >> 2);
        int n = cbase + wid*8 + (lane & 3)*2;
        if (n < NT1){
            float b0 = __ldg(bd2 + n);
            dec[(size_t)r0*NT1 + n]     = c[mt][0] + b0;
            dec[(size_t)(r0+8)*NT1 + n] = c[mt][2] + b0;
        }
        if (n + 1 < NT1){
            float b1v = __ldg(bd2 + n + 1);
            dec[(size_t)r0*NT1 + n + 1]     = c[mt][1] + b1v;
            dec[(size_t)(r0+8)*NT1 + n + 1] = c[mt][3] + b1v;
        }
    }
}

// ---------------- launch -----------------------------------------------------
extern "C" void kernel_launch(void* const* d_in, const int* in_sizes, int n_in,
                              void* d_out, int out_size){
    const int*   tags = (const int*)  d_in[0];
    const float* fc   = (const float*)d_in[1];
    const float* lng  = (const float*)d_in[2];
    const float* lnb  = (const float*)d_in[3];
    const float* w1   = (const float*)d_in[4];
    const float* b1   = (const float*)d_in[5];
    const float* ln2g = (const float*)d_in[6];
    const float* ln2b = (const float*)d_in[7];
    const float* we1  = (const float*)d_in[8];
    const float* be1  = (const float*)d_in[9];
    const float* we2  = (const float*)d_in[10];
    const float* be2  = (const float*)d_in[11];
    const float* wd1  = (const float*)d_in[12];
    const float* bd1  = (const float*)d_in[13];
    const float* wd2  = (const float*)d_in[14];
    const float* bd2  = (const float*)d_in[15];
    float* out = (float*)d_out;

    float *p_counts, *p_h2, *p_h3, *p_enc, *p_pbuf;
    int* p_istat;
    cudaGetSymbolAddress((void**)&p_counts, g_counts);
    cudaGetSymbolAddress((void**)&p_istat,  g_istat);
    cudaGetSymbolAddress((void**)&p_h2,     g_h2);
    cudaGetSymbolAddress((void**)&p_h3,     g_h3);
    cudaGetSymbolAddress((void**)&p_enc,    g_encb);
    cudaGetSymbolAddress((void**)&p_pbuf,   g_pbuf);

    static int attr_set = 0;
    if (!attr_set){
        cudaFuncSetAttribute(k4_mma, cudaFuncAttributeMaxDynamicSharedMemorySize, 2*BUFB);
        attr_set = 1;
    }

    cudaMemsetAsync(p_counts, 0, (size_t)NT*B*sizeof(float));
    cudaMemsetAsync(p_istat,  0, 128*sizeof(int));
    k1_scatter<<<32, 256>>>(tags);
    k3_y<<<313, 256>>>(fc, lng, lnb, out);

    // GEMM1 on tensor cores (reads y from out) — R12-proven k4
    k4_mma<<<dim3(8, KB4), 256, 2*BUFB>>>(out, w1);
    k5_fused<<<64, 256>>>(b1, ln2g, ln2b);

    // h2 @ we1 (1024->1024) + gelu
    sg_part<1024, 1024, 32><<<dim3(16, 32), 256>>>(p_h2, we1, p_pbuf);
    sg_reduce<32, 1024, true><<<256, 256>>>(p_pbuf, be1, p_h3, (float*)0);
    // h3 @ we2 (1024->256) -> enc (output #2)
    sg_part<1024, 256, 32><<<dim3(4, 32), 256>>>(p_h3, we2, p_pbuf);
    sg_reduce<32, 256, false><<<64, 256>>>(p_pbuf, be2, out + ENC_OFF, p_enc);
    // enc @ wd1 (256->1024) + gelu -> dd (bf16 split)
    sg_part<256, 1024, 32><<<dim3(16, 8), 256>>>(p_enc, wd1, p_pbuf);
    sg_reduce_dd<<<256, 256>>>(p_pbuf, bd1);

    // decoder GEMM -> dec (output #3), NB=64 full-K direct store + bias
    k10_mma<<<313, 256, K10_SMEM>>>(wd2, bd2, out + DEC_OFF);
}